// round 6
// baseline (speedup 1.0000x reference)
#include <cuda_runtime.h>
#include <cuda_bf16.h>

#define N_NODES 100000
#define B_DIM   16

// Scratch: transposed x and accumulator, [N, B] layout so one edge's 16
// batch lanes are 64 contiguous bytes.
__device__ float g_xt[N_NODES * B_DIM];
__device__ float g_yt[N_NODES * B_DIM];

// ---------------------------------------------------------------------------
// Kernel 1: transpose x [B,N] -> g_xt [N,B], and zero g_yt (zeroing HERE,
// right before the edge kernel's atomics, keeps accumulator lines hot/dirty
// in L2 — proven load-bearing R2 vs R4).
// Tile: 256 nodes x 16 batches per block; each thread issues 4 independent
// float4 loads before the sync (MLP=4) to hide DRAM latency.
// ---------------------------------------------------------------------------
__global__ void __launch_bounds__(256)
transpose_zero_kernel(const float* __restrict__ x, int N) {
    __shared__ float tile[16][260];  // [b][n in tile]
    const int n0 = blockIdx.x * 256;
    const int tid = threadIdx.x;     // 0..255
    const int N4 = N >> 2;           // N divisible by 4

    // Load: 1024 float4s (16 b x 64 quads), 4 independent loads per thread.
    float4 v[4];
    #pragma unroll
    for (int p = 0; p < 4; p++) {
        int idx = p * 256 + tid;     // 0..1023
        int b  = idx >> 6;           // 0..15
        int nq = idx & 63;           // quad within tile
        int gq = (n0 >> 2) + nq;
        v[p] = make_float4(0.f, 0.f, 0.f, 0.f);
        if (gq < N4) v[p] = ((const float4*)x)[b * N4 + gq];
    }
    #pragma unroll
    for (int p = 0; p < 4; p++) {
        int idx = p * 256 + tid;
        int b  = idx >> 6;
        int nq = idx & 63;
        tile[b][4 * nq + 0] = v[p].x;
        tile[b][4 * nq + 1] = v[p].y;
        tile[b][4 * nq + 2] = v[p].z;
        tile[b][4 * nq + 3] = v[p].w;
    }
    __syncthreads();

    // Store: thread -> (node, batch-quad) across 4 passes; each instruction's
    // 32 lanes write 512 contiguous bytes.
    #pragma unroll
    for (int p = 0; p < 4; p++) {
        int t = p * 256 + tid;       // 0..1023
        int n = t >> 2;              // node in tile 0..255
        int q = t & 3;               // 0..3
        int nn = n0 + n;
        if (nn < N) {
            float4 w;
            w.x = tile[4 * q + 0][n];
            w.y = tile[4 * q + 1][n];
            w.z = tile[4 * q + 2][n];
            w.w = tile[4 * q + 3][n];
            *(float4*)&g_xt[nn * B_DIM + 4 * q] = w;
            *(float4*)&g_yt[nn * B_DIM + 4 * q] = make_float4(0.f, 0.f, 0.f, 0.f);
        }
    }
}

// ---------------------------------------------------------------------------
// Kernel 2: edge stage (R2/R5 proven version, FROZEN).
// One thread per (edge, batch-quad): float4 gather, 4x (fma, tanh, blend),
// ONE red.global.add.v4.f32.
// ---------------------------------------------------------------------------
__global__ void __launch_bounds__(256)
edge_kernel(const int*   __restrict__ src_idx,
            const int*   __restrict__ dst_idx,
            const float* __restrict__ edge_alpha,
            const float* __restrict__ edge_w,
            const float* __restrict__ edge_b,
            int E) {
    int t = blockIdx.x * blockDim.x + threadIdx.x;
    if (t >= E * 4) return;
    int e = t >> 2;
    int q = t & 3;

    int   s  = src_idx[e];
    int   d  = dst_idx[e];
    float w  = edge_w[e];
    float bb = edge_b[e];
    float a  = edge_alpha[e];

    float4 xv = *(const float4*)&g_xt[s * B_DIM + 4 * q];

    float l0 = fmaf(w, xv.x, bb);
    float l1 = fmaf(w, xv.y, bb);
    float l2 = fmaf(w, xv.z, bb);
    float l3 = fmaf(w, xv.w, bb);

    float t0, t1, t2, t3;
    asm("tanh.approx.f32 %0, %1;" : "=f"(t0) : "f"(l0));
    asm("tanh.approx.f32 %0, %1;" : "=f"(t1) : "f"(l1));
    asm("tanh.approx.f32 %0, %1;" : "=f"(t2) : "f"(l2));
    asm("tanh.approx.f32 %0, %1;" : "=f"(t3) : "f"(l3));

    float m0 = fmaf(a, t0 - l0, l0);
    float m1 = fmaf(a, t1 - l1, l1);
    float m2 = fmaf(a, t2 - l2, l2);
    float m3 = fmaf(a, t3 - l3, l3);

    size_t gaddr = __cvta_generic_to_global(&g_yt[d * B_DIM + 4 * q]);
    asm volatile("red.global.add.v4.f32 [%0], {%1, %2, %3, %4};"
                 :: "l"(gaddr), "f"(m0), "f"(m1), "f"(m2), "f"(m3)
                 : "memory");
}

// ---------------------------------------------------------------------------
// Kernel 3: node stage + transpose back. 256 nodes x 16 batches per block,
// 4 independent float4 loads per thread (MLP=4). No zeroing here (R4 lesson).
// ---------------------------------------------------------------------------
__global__ void __launch_bounds__(256)
node_kernel(const float* __restrict__ node_alpha,
            const float* __restrict__ node_w,
            const float* __restrict__ node_b,
            float* __restrict__ out, int N) {
    __shared__ float tile[16][260];
    const int n0 = blockIdx.x * 256;
    const int tid = threadIdx.x;
    const int N4 = N >> 2;

    // Load: thread -> (node, batch-quad) across 4 passes, independent loads.
    float4 v[4];
    #pragma unroll
    for (int p = 0; p < 4; p++) {
        int t = p * 256 + tid;
        int n = t >> 2;
        int q = t & 3;
        int nn = n0 + n;
        v[p] = make_float4(0.f, 0.f, 0.f, 0.f);
        if (nn < N) v[p] = *(const float4*)&g_yt[nn * B_DIM + 4 * q];
    }
    #pragma unroll
    for (int p = 0; p < 4; p++) {
        int t = p * 256 + tid;
        int n = t >> 2;
        int q = t & 3;
        tile[4 * q + 0][n] = v[p].x;
        tile[4 * q + 1][n] = v[p].y;
        tile[4 * q + 2][n] = v[p].z;
        tile[4 * q + 3][n] = v[p].w;
    }
    __syncthreads();

    // Store: 1024 float4s (16 b x 64 quads), math per element, coalesced.
    #pragma unroll
    for (int p = 0; p < 4; p++) {
        int idx = p * 256 + tid;
        int b  = idx >> 6;
        int nq = idx & 63;
        int gq = (n0 >> 2) + nq;
        if (gq < N4) {
            float4 r;
            #pragma unroll
            for (int k = 0; k < 4; k++) {
                int nl = 4 * nq + k;         // node within tile
                int ng = n0 + nl;            // global node
                float y   = tile[b][nl];
                float w   = node_w[ng];
                float bb  = node_b[ng];
                float a   = node_alpha[ng];
                float lin = fmaf(w, y, bb);
                float th;
                asm("tanh.approx.f32 %0, %1;" : "=f"(th) : "f"(lin));
                ((float*)&r)[k] = fmaf(a, th - lin, lin);
            }
            ((float4*)out)[b * N4 + gq] = r;
        }
    }
}

// ---------------------------------------------------------------------------
// Input order: x, src_idx, dst_idx, edge_alpha, edge_w, edge_b,
// node_alpha, node_w, node_b. Output: float32 [B, N].
// ---------------------------------------------------------------------------
extern "C" void kernel_launch(void* const* d_in, const int* in_sizes, int n_in,
                              void* d_out, int out_size) {
    const float* x          = (const float*)d_in[0];
    const int*   src_idx    = (const int*)  d_in[1];
    const int*   dst_idx    = (const int*)  d_in[2];
    const float* edge_alpha = (const float*)d_in[3];
    const float* edge_w     = (const float*)d_in[4];
    const float* edge_b     = (const float*)d_in[5];
    const float* node_alpha = (const float*)d_in[6];
    const float* node_w     = (const float*)d_in[7];
    const float* node_b     = (const float*)d_in[8];
    float* out = (float*)d_out;

    const int E = in_sizes[1];
    const int N = in_sizes[6];

    int n_tiles = (N + 255) / 256;

    transpose_zero_kernel<<<n_tiles, 256>>>(x, N);

    int total = E * 4;
    edge_kernel<<<(total + 255) / 256, 256>>>(src_idx, dst_idx, edge_alpha,
                                              edge_w, edge_b, E);

    node_kernel<<<n_tiles, 256>>>(node_alpha, node_w, node_b, out, N);
}

// round 7
// speedup vs baseline: 1.0283x; 1.0283x over previous
#include <cuda_runtime.h>
#include <cuda_bf16.h>

#define N_NODES 100000
#define B_DIM   16

// Scratch: transposed x and accumulator, [N, B] layout so one edge's 16
// batch lanes are 64 contiguous bytes.
__device__ float g_xt[N_NODES * B_DIM];
__device__ float g_yt[N_NODES * B_DIM];

// ---------------------------------------------------------------------------
// Kernel 1: transpose x [B,N] -> g_xt [N,B], and zero g_yt (zeroing HERE,
// right before the edge kernel's atomics — proven load-bearing R2 vs R4).
// FROZEN at R6 form.
// ---------------------------------------------------------------------------
__global__ void __launch_bounds__(256)
transpose_zero_kernel(const float* __restrict__ x, int N) {
    __shared__ float tile[16][260];
    const int n0 = blockIdx.x * 256;
    const int tid = threadIdx.x;
    const int N4 = N >> 2;

    float4 v[4];
    #pragma unroll
    for (int p = 0; p < 4; p++) {
        int idx = p * 256 + tid;
        int b  = idx >> 6;
        int nq = idx & 63;
        int gq = (n0 >> 2) + nq;
        v[p] = make_float4(0.f, 0.f, 0.f, 0.f);
        if (gq < N4) v[p] = ((const float4*)x)[b * N4 + gq];
    }
    #pragma unroll
    for (int p = 0; p < 4; p++) {
        int idx = p * 256 + tid;
        int b  = idx >> 6;
        int nq = idx & 63;
        tile[b][4 * nq + 0] = v[p].x;
        tile[b][4 * nq + 1] = v[p].y;
        tile[b][4 * nq + 2] = v[p].z;
        tile[b][4 * nq + 3] = v[p].w;
    }
    __syncthreads();

    #pragma unroll
    for (int p = 0; p < 4; p++) {
        int t = p * 256 + tid;
        int n = t >> 2;
        int q = t & 3;
        int nn = n0 + n;
        if (nn < N) {
            float4 w;
            w.x = tile[4 * q + 0][n];
            w.y = tile[4 * q + 1][n];
            w.z = tile[4 * q + 2][n];
            w.w = tile[4 * q + 3][n];
            *(float4*)&g_xt[nn * B_DIM + 4 * q] = w;
            *(float4*)&g_yt[nn * B_DIM + 4 * q] = make_float4(0.f, 0.f, 0.f, 0.f);
        }
    }
}

// ---------------------------------------------------------------------------
// Kernel 2: edge stage — 2 tasks per thread (split-grid) for latency overlap.
// Each task keeps the proven (edge, batch-quad) mapping: 4 consecutive lanes
// share one contiguous 64B node row on both gather and RED.
// ---------------------------------------------------------------------------
__global__ void __launch_bounds__(256)
edge_kernel(const int*   __restrict__ src_idx,
            const int*   __restrict__ dst_idx,
            const float* __restrict__ edge_alpha,
            const float* __restrict__ edge_w,
            const float* __restrict__ edge_b,
            int E, int half) {
    int t0 = blockIdx.x * blockDim.x + threadIdx.x;
    if (t0 >= half) return;
    int t1 = t0 + half;
    const int T = E * 4;
    bool has1 = (t1 < T);

    int eA = t0 >> 2, qA = t0 & 3;
    int eB = t1 >> 2, qB = t1 & 3;

    // Batched param loads (independent).
    int   sA = __ldg(&src_idx[eA]);
    int   dA = __ldg(&dst_idx[eA]);
    float wA = __ldg(&edge_w[eA]);
    float bA = __ldg(&edge_b[eA]);
    float aA = __ldg(&edge_alpha[eA]);

    int eBs = has1 ? eB : eA;   // safe index for inactive lane
    int   sB = __ldg(&src_idx[eBs]);
    int   dB = __ldg(&dst_idx[eBs]);
    float wB = __ldg(&edge_w[eBs]);
    float bB = __ldg(&edge_b[eBs]);
    float aB = __ldg(&edge_alpha[eBs]);

    // Two independent gathers in flight.
    float4 xA = __ldg((const float4*)&g_xt[sA * B_DIM + 4 * qA]);
    float4 xB = __ldg((const float4*)&g_xt[sB * B_DIM + 4 * qB]);

    // Task A math + RED
    {
        float l0 = fmaf(wA, xA.x, bA);
        float l1 = fmaf(wA, xA.y, bA);
        float l2 = fmaf(wA, xA.z, bA);
        float l3 = fmaf(wA, xA.w, bA);
        float h0, h1, h2, h3;
        asm("tanh.approx.f32 %0, %1;" : "=f"(h0) : "f"(l0));
        asm("tanh.approx.f32 %0, %1;" : "=f"(h1) : "f"(l1));
        asm("tanh.approx.f32 %0, %1;" : "=f"(h2) : "f"(l2));
        asm("tanh.approx.f32 %0, %1;" : "=f"(h3) : "f"(l3));
        float m0 = fmaf(aA, h0 - l0, l0);
        float m1 = fmaf(aA, h1 - l1, l1);
        float m2 = fmaf(aA, h2 - l2, l2);
        float m3 = fmaf(aA, h3 - l3, l3);
        size_t gaddr = __cvta_generic_to_global(&g_yt[dA * B_DIM + 4 * qA]);
        asm volatile("red.global.add.v4.f32 [%0], {%1, %2, %3, %4};"
                     :: "l"(gaddr), "f"(m0), "f"(m1), "f"(m2), "f"(m3)
                     : "memory");
    }

    // Task B math + RED
    if (has1) {
        float l0 = fmaf(wB, xB.x, bB);
        float l1 = fmaf(wB, xB.y, bB);
        float l2 = fmaf(wB, xB.z, bB);
        float l3 = fmaf(wB, xB.w, bB);
        float h0, h1, h2, h3;
        asm("tanh.approx.f32 %0, %1;" : "=f"(h0) : "f"(l0));
        asm("tanh.approx.f32 %0, %1;" : "=f"(h1) : "f"(l1));
        asm("tanh.approx.f32 %0, %1;" : "=f"(h2) : "f"(l2));
        asm("tanh.approx.f32 %0, %1;" : "=f"(h3) : "f"(l3));
        float m0 = fmaf(aB, h0 - l0, l0);
        float m1 = fmaf(aB, h1 - l1, l1);
        float m2 = fmaf(aB, h2 - l2, l2);
        float m3 = fmaf(aB, h3 - l3, l3);
        size_t gaddr = __cvta_generic_to_global(&g_yt[dB * B_DIM + 4 * qB]);
        asm volatile("red.global.add.v4.f32 [%0], {%1, %2, %3, %4};"
                     :: "l"(gaddr), "f"(m0), "f"(m1), "f"(m2), "f"(m3)
                     : "memory");
    }
}

// ---------------------------------------------------------------------------
// Kernel 3: node stage + transpose back. FROZEN at R6 form.
// ---------------------------------------------------------------------------
__global__ void __launch_bounds__(256)
node_kernel(const float* __restrict__ node_alpha,
            const float* __restrict__ node_w,
            const float* __restrict__ node_b,
            float* __restrict__ out, int N) {
    __shared__ float tile[16][260];
    const int n0 = blockIdx.x * 256;
    const int tid = threadIdx.x;
    const int N4 = N >> 2;

    float4 v[4];
    #pragma unroll
    for (int p = 0; p < 4; p++) {
        int t = p * 256 + tid;
        int n = t >> 2;
        int q = t & 3;
        int nn = n0 + n;
        v[p] = make_float4(0.f, 0.f, 0.f, 0.f);
        if (nn < N) v[p] = *(const float4*)&g_yt[nn * B_DIM + 4 * q];
    }
    #pragma unroll
    for (int p = 0; p < 4; p++) {
        int t = p * 256 + tid;
        int n = t >> 2;
        int q = t & 3;
        tile[4 * q + 0][n] = v[p].x;
        tile[4 * q + 1][n] = v[p].y;
        tile[4 * q + 2][n] = v[p].z;
        tile[4 * q + 3][n] = v[p].w;
    }
    __syncthreads();

    #pragma unroll
    for (int p = 0; p < 4; p++) {
        int idx = p * 256 + tid;
        int b  = idx >> 6;
        int nq = idx & 63;
        int gq = (n0 >> 2) + nq;
        if (gq < N4) {
            float4 r;
            #pragma unroll
            for (int k = 0; k < 4; k++) {
                int nl = 4 * nq + k;
                int ng = n0 + nl;
                float y   = tile[b][nl];
                float w   = node_w[ng];
                float bb  = node_b[ng];
                float a   = node_alpha[ng];
                float lin = fmaf(w, y, bb);
                float th;
                asm("tanh.approx.f32 %0, %1;" : "=f"(th) : "f"(lin));
                ((float*)&r)[k] = fmaf(a, th - lin, lin);
            }
            ((float4*)out)[b * N4 + gq] = r;
        }
    }
}

// ---------------------------------------------------------------------------
// Input order: x, src_idx, dst_idx, edge_alpha, edge_w, edge_b,
// node_alpha, node_w, node_b. Output: float32 [B, N].
// ---------------------------------------------------------------------------
extern "C" void kernel_launch(void* const* d_in, const int* in_sizes, int n_in,
                              void* d_out, int out_size) {
    const float* x          = (const float*)d_in[0];
    const int*   src_idx    = (const int*)  d_in[1];
    const int*   dst_idx    = (const int*)  d_in[2];
    const float* edge_alpha = (const float*)d_in[3];
    const float* edge_w     = (const float*)d_in[4];
    const float* edge_b     = (const float*)d_in[5];
    const float* node_alpha = (const float*)d_in[6];
    const float* node_w     = (const float*)d_in[7];
    const float* node_b     = (const float*)d_in[8];
    float* out = (float*)d_out;

    const int E = in_sizes[1];
    const int N = in_sizes[6];

    int n_tiles = (N + 255) / 256;

    transpose_zero_kernel<<<n_tiles, 256>>>(x, N);

    const int T = E * 4;
    // half rounded up to a block multiple so grid*256 == half exactly
    int half = ((T + 1) / 2 + 255) & ~255;
    int blocks = half / 256;
    edge_kernel<<<blocks, 256>>>(src_idx, dst_idx, edge_alpha,
                                 edge_w, edge_b, E, half);

    node_kernel<<<n_tiles, 256>>>(node_alpha, node_w, node_b, out, N);
}